// round 13
// baseline (speedup 1.0000x reference)
#include <cuda_runtime.h>
#include <cuda_fp16.h>
#include <cstdint>

#define NH   8
#define FD   128
#define DVD  16
#define LL   50
#define NT   256

// ---------------- smem layout (bytes), per-CTA (1 batch, M=64) ----------------
#define OFF_SP   0                      // p_all [64][8] f32 (+c folded)
#define OFF_SR   2048                   // r_all [64][8] f32
#define OFF_XHI  4096                   // X hi [64][256B] swizzled fp16
#define OFF_XLO  (OFF_XHI + 16384)
#define OFF_YHI  (OFF_XLO + 16384)      // Y hi [64][256B]
#define OFF_YLO  (OFF_YHI + 16384)      // Y lo [64][256B]
#define OFF_V    (OFF_YLO + 16384)      // V f32 [64][16]
#define OFF_P    (OFF_V + 4096)         // P f32 [64][65]
#define SMEM_TOTAL (OFF_P + 64*65*4)    // 90368  (x2 CTAs = 180736 < 227KB)

// ------------- precomputed data -------------
__device__ float g_Atmp[NH][FD][FD];                     // A = Wq Wk^T (f32)
__device__ __align__(16) uint4 g_fragAhi[NH * 8 * 8 * 32]; // [h][k][tp][lane]
__device__ __align__(16) uint4 g_fragAlo[NH * 8 * 8 * 32];
__device__ __align__(16) uint4 g_fragWhi[NH * 8 * 32];     // [h][k][lane]
__device__ __align__(16) uint4 g_fragWlo[NH * 8 * 32];
__device__ float g_u[NH][FD];
__device__ float g_w[NH][FD];
__device__ float g_c[NH];

// swizzled byte offset in a [rows][128 f16] tile (256B rows, 16B-chunk XOR)
__host__ __device__ __forceinline__ uint32_t xoff(int r, int c) {
    return (uint32_t)r * 256u
         + (uint32_t)(((((c >> 3) ^ (r & 7))) << 4) + (c & 7) * 2);
}

// ---------------- PTX helpers ----------------
__device__ __forceinline__ uint32_t smem_u32(const void* p) {
    uint32_t a;
    asm("{ .reg .u64 t; cvta.to.shared.u64 t, %1; cvt.u32.u64 %0, t; }"
        : "=r"(a) : "l"(p));
    return a;
}
__device__ __forceinline__ void ldsm_x4(uint32_t a[4], uint32_t addr) {
    asm volatile("ldmatrix.sync.aligned.m8n8.x4.shared.b16 {%0,%1,%2,%3}, [%4];"
                 : "=r"(a[0]), "=r"(a[1]), "=r"(a[2]), "=r"(a[3]) : "r"(addr));
}
__device__ __forceinline__ void ldsm_x2(uint32_t a[2], uint32_t addr) {
    asm volatile("ldmatrix.sync.aligned.m8n8.x2.shared.b16 {%0,%1}, [%2];"
                 : "=r"(a[0]), "=r"(a[1]) : "r"(addr));
}
__device__ __forceinline__ void mma_f32(float c[4], const uint32_t a[4],
                                        const uint32_t b0, const uint32_t b1) {
    asm volatile(
        "mma.sync.aligned.m16n8k16.row.col.f32.f16.f16.f32 "
        "{%0,%1,%2,%3}, {%4,%5,%6,%7}, {%8,%9}, {%0,%1,%2,%3};"
        : "+f"(c[0]), "+f"(c[1]), "+f"(c[2]), "+f"(c[3])
        : "r"(a[0]), "r"(a[1]), "r"(a[2]), "r"(a[3]), "r"(b0), "r"(b1));
}
__device__ __forceinline__ void mma_f16(uint32_t& d0, uint32_t& d1,
                                        const uint32_t a[4],
                                        const uint32_t b0, const uint32_t b1) {
    asm volatile(
        "mma.sync.aligned.m16n8k16.row.col.f16.f16.f16.f16 "
        "{%0,%1}, {%2,%3,%4,%5}, {%6,%7}, {%0,%1};"
        : "+r"(d0), "+r"(d1)
        : "r"(a[0]), "r"(a[1]), "r"(a[2]), "r"(a[3]), "r"(b0), "r"(b1));
}
__device__ __forceinline__ void fold_corr(float c[4], uint32_t d0, uint32_t d1) {
    float2 f0 = __half22float2(*(__half2*)&d0);
    float2 f1 = __half22float2(*(__half2*)&d1);
    c[0] += f0.x;  c[1] += f0.y;  c[2] += f1.x;  c[3] += f1.y;
}
__device__ __forceinline__ uint32_t pack_f16(float a, float b) {
    __half2 t = __floats2half2_rn(a, b);
    return *(uint32_t*)&t;
}

// ---------------------------------------------------------------------------
// Kernel 1a: A = Wq Wk^T (f32) + bias dots
// ---------------------------------------------------------------------------
__global__ void precompute1_kernel(const float* __restrict__ Wq,
                                   const float* __restrict__ bq,
                                   const float* __restrict__ Wk,
                                   const float* __restrict__ bk) {
    const int h     = blockIdx.x;
    const int slice = blockIdx.y;
    const int tid   = threadIdx.x;
    const float* wq = Wq + h * FD * 128;
    const float* wk = Wk + h * FD * 128;

    #pragma unroll
    for (int r = 0; r < 8; r++) {
        int o  = slice * 2048 + r * 256 + tid;
        int f  = o >> 7;
        int fp = o & 127;
        const float* qrow = wq + f * 128;
        const float* krow = wk + fp * 128;
        float acc = 0.f;
        #pragma unroll 8
        for (int e = 0; e < 128; e++) acc += qrow[e] * krow[e];
        g_Atmp[h][f][fp] = acc;
    }
    if (slice == 0) {
        if (tid < FD) {
            float au = 0.f, aw = 0.f;
            #pragma unroll 8
            for (int e = 0; e < 128; e++) {
                au += wq[tid * 128 + e] * bk[h * 128 + e];
                aw += wk[tid * 128 + e] * bq[h * 128 + e];
            }
            g_u[h][tid] = au;
            g_w[h][tid] = aw;
        }
        if (tid == 128) {
            float c = 0.f;
            for (int e = 0; e < 128; e++) c += bq[h * 128 + e] * bk[h * 128 + e];
            g_c[h] = c;
        }
    }
}

// ---------------------------------------------------------------------------
// Kernel 1b: build ldmatrix-order fragments for At (hi/lo) and Wvt (hi/lo).
// Stages swizzled tiles in smem and runs the EXACT consumer ldsm addressing.
// ---------------------------------------------------------------------------
#define P2_AHI 0
#define P2_ALO 32768
#define P2_WHI 65536
#define P2_WLO 69632
#define P2_SMEM 73728

__global__ void precompute2_kernel(const float* __restrict__ Wv) {
    extern __shared__ char smc[];
    const uint32_t sb = smem_u32(smc);
    const int h    = blockIdx.x;
    const int tid  = threadIdx.x;
    const int wid  = tid >> 5;
    const int lane = tid & 31;

    // stage At (row fp, col f) hi/lo swizzled
    for (int i = tid; i < FD * FD; i += NT) {
        int fp = i >> 7, f = i & 127;
        float v = g_Atmp[h][f][fp];
        __half hi = __float2half_rn(v);
        float rem = v - __half2float(hi);
        uint32_t off = xoff(fp, f);
        *(__half*)(smc + P2_AHI + off) = hi;
        *(__half*)(smc + P2_ALO + off) = __float2half_rn(rem);
    }
    // stage Wvt (row dv, col f) hi/lo swizzled
    for (int i = tid; i < DVD * FD; i += NT) {
        int dv = i >> 7, f = i & 127;
        float v = Wv[h * FD * DVD + f * DVD + dv];
        __half hi = __float2half_rn(v);
        float rem = v - __half2float(hi);
        uint32_t off = xoff(dv, f);
        *(__half*)(smc + P2_WHI + off) = hi;
        *(__half*)(smc + P2_WLO + off) = __float2half_rn(rem);
    }
    __syncthreads();

    const int i15   = lane & 15;
    const int blr   = i15 & 7;
    const int bhalf = i15 >> 3;
    const uint32_t bRowOff = (uint32_t)blr * 256u;
    const uint32_t bPair   = (uint32_t)((lane >> 4) << 11);

    // warp w emulates tile-pair tp = w for all k
    const int tp = wid;
    #pragma unroll
    for (int k = 0; k < 8; k++) {
        uint32_t cb = (uint32_t)(((2 * k + bhalf) ^ blr) << 4);
        uint32_t o = bRowOff + cb + bPair + (uint32_t)(tp * 4096);
        uint32_t bh[4], bl[4];
        ldsm_x4(bh, sb + P2_AHI + o);
        ldsm_x4(bl, sb + P2_ALO + o);
        int idx = ((h * 8 + k) * 8 + tp) * 32 + lane;
        g_fragAhi[idx] = make_uint4(bh[0], bh[1], bh[2], bh[3]);
        g_fragAlo[idx] = make_uint4(bl[0], bl[1], bl[2], bl[3]);
        if (wid == 0) {
            uint32_t ow = bRowOff + cb + bPair;
            uint32_t wh[4], wl[4];
            ldsm_x4(wh, sb + P2_WHI + ow);
            ldsm_x4(wl, sb + P2_WLO + ow);
            int wi = (h * 8 + k) * 32 + lane;
            g_fragWhi[wi] = make_uint4(wh[0], wh[1], wh[2], wh[3]);
            g_fragWlo[wi] = make_uint4(wl[0], wl[1], wl[2], wl[3]);
        }
    }
}

// ---------------------------------------------------------------------------
// Kernel 2: HMMA attention, 256 threads, 1 batch per CTA (M = 64), 2 CTAs/SM.
// B-operands of GEMM1 come straight from global fragment arrays (LDG.128).
// ---------------------------------------------------------------------------
__global__ void __launch_bounds__(NT, 2)
attn_mma_kernel(const float* __restrict__ hid,
                const float* __restrict__ bv,
                float* __restrict__ out) {
    extern __shared__ char smc[];
    const uint32_t sb = smem_u32(smc);
    const int tid  = threadIdx.x;
    const int wid  = tid >> 5;
    const int lane = tid & 31;
    const int bid  = blockIdx.x;

    float* spf = (float*)(smc + OFF_SP);   // [64][8]
    float* srf = (float*)(smc + OFF_SR);   // [64][8]
    float* sVf = (float*)(smc + OFF_V);    // [64][16]
    float* sPf = (float*)(smc + OFF_P);    // [64][65]

    const float* xg = hid + (long long)bid * (LL * FD);

    // ---- load x, fp16 hi/lo split, swizzled ----
    for (int i = tid; i < 64 * 64; i += NT) {
        int l  = i >> 6;
        int cp = (i & 63) * 2;
        float v0 = 0.f, v1 = 0.f;
        if (l < LL) {
            const float* xr = xg + l * FD + cp;
            v0 = xr[0]; v1 = xr[1];
        }
        __half h0 = __float2half_rn(v0), h1 = __float2half_rn(v1);
        float r0 = v0 - __half2float(h0), r1 = v1 - __half2float(h1);
        uint32_t off = xoff(l, cp);
        __half2 hw = __halves2half2(h0, h1);
        *(uint32_t*)(smc + OFF_XHI + off) = *(uint32_t*)&hw;
        *(uint32_t*)(smc + OFF_XLO + off) = pack_f16(r0, r1);
    }

    // ---- all-head p/r bias dots (once) ----
    if (tid < 128) {
        int l  = tid >> 1;
        int pr = tid & 1;
        float acc[8];
        #pragma unroll
        for (int h2 = 0; h2 < 8; h2++) acc[h2] = 0.f;
        if (l < LL) {
            const float* xr = xg + l * FD;
            const float* vb = pr ? &g_w[0][0] : &g_u[0][0];
            #pragma unroll 2
            for (int f = 0; f < FD; f += 4) {
                float4 xq = *(const float4*)(xr + f);
                #pragma unroll
                for (int h2 = 0; h2 < 8; h2++) {
                    const float* v = vb + h2 * FD + f;
                    acc[h2] += xq.x * v[0] + xq.y * v[1] + xq.z * v[2] + xq.w * v[3];
                }
            }
        }
        float* dst = pr ? srf : spf;
        #pragma unroll
        for (int h2 = 0; h2 < 8; h2++)
            dst[l * 8 + h2] = acc[h2] + (pr ? 0.f : g_c[h2]);
    }

    // ---- ldmatrix lane-address components ----
    const int lr    = lane & 7;
    const int quad  = lane >> 3;
    const int ahalf = quad >> 1;
    const int i15   = lane & 15;
    const int blr   = i15 & 7;
    const int bhalf = i15 >> 3;
    const uint32_t bRowOff = (uint32_t)blr * 256u;
    const uint32_t bPair   = (uint32_t)((lane >> 4) << 11);
    const int g  = lane >> 2;
    const int tg = lane & 3;

    // GEMM1: warp = m16-slice (ms) x n-half (nh: 8 Y tiles + 1 V tile)
    const int ms = wid & 3;
    const int nh = wid >> 2;
    const uint32_t aRow1 = (uint32_t)(ms * 16 + lr + ((quad & 1) << 3)) * 256u;
    // GEMM2 (wid<4): warp = m16-slice over all 7 n-tiles
    const uint32_t aRow2 = (uint32_t)(wid * 16 + lr + ((quad & 1) << 3)) * 256u;

    __syncthreads();                                       // X + biases ready

    for (int h = 0; h < NH; h++) {
        // ======== GEMM1: Y = X·Atᵀ + V rider (B frags via LDG) ========
        float cY[8][4];
        uint32_t cc[8][2];
        float cV[4];
        uint32_t cVc[2];
        #pragma unroll
        for (int j = 0; j < 8; j++) {
            #pragma unroll
            for (int q = 0; q < 4; q++) cY[j][q] = 0.f;
            cc[j][0] = 0u; cc[j][1] = 0u;
        }
        #pragma unroll
        for (int q = 0; q < 4; q++) cV[q] = 0.f;
        cVc[0] = 0u; cVc[1] = 0u;

        #pragma unroll
        for (int k = 0; k < 8; k++) {
            uint32_t ca = (uint32_t)(((2 * k + ahalf) ^ lr) << 4);
            uint32_t ahi[4], alo[4];
            ldsm_x4(ahi, sb + OFF_XHI + aRow1 + ca);
            ldsm_x4(alo, sb + OFF_XLO + aRow1 + ca);
            const int kb = ((h * 8 + k) * 8) * 32 + lane;
            #pragma unroll
            for (int jp = 0; jp < 4; jp++) {
                const int tp = nh * 4 + jp;
                uint4 b4 = g_fragAhi[kb + tp * 32];
                uint4 l4 = g_fragAlo[kb + tp * 32];
                const int j0 = jp * 2, j1 = jp * 2 + 1;
                mma_f32(cY[j0], ahi, b4.x, b4.y);
                mma_f16(cc[j0][0], cc[j0][1], ahi, l4.x, l4.y);
                mma_f16(cc[j0][0], cc[j0][1], alo, b4.x, b4.y);
                mma_f32(cY[j1], ahi, b4.z, b4.w);
                mma_f16(cc[j1][0], cc[j1][1], ahi, l4.z, l4.w);
                mma_f16(cc[j1][0], cc[j1][1], alo, b4.z, b4.w);
            }
            {
                const uint2* wp = (const uint2*)g_fragWhi;
                const uint2* lp = (const uint2*)g_fragWlo;
                const int wi = ((h * 8 + k) * 32 + lane) * 2 + nh;
                uint2 wh = wp[wi];
                uint2 wl = lp[wi];
                mma_f32(cV, ahi, wh.x, wh.y);
                mma_f16(cVc[0], cVc[1], ahi, wl.x, wl.y);
                mma_f16(cVc[0], cVc[1], alo, wh.x, wh.y);
            }
        }

        // ---- fold + write Y (hi/lo) and V ----
        {
            const int rbase = ms * 16;
            #pragma unroll
            for (int j = 0; j < 8; j++) {
                fold_corr(cY[j], cc[j][0], cc[j][1]);
                int col = nh * 64 + j * 8 + tg * 2;
                uint32_t o0 = xoff(rbase + g, col);
                uint32_t o1 = xoff(rbase + 8 + g, col);
                float y0 = cY[j][0], y1 = cY[j][1];
                float y2 = cY[j][2], y3 = cY[j][3];
                __half h0 = __float2half_rn(y0), h1 = __float2half_rn(y1);
                __half h2 = __float2half_rn(y2), h3 = __float2half_rn(y3);
                __half2 w0 = __halves2half2(h0, h1);
                __half2 w1 = __halves2half2(h2, h3);
                *(uint32_t*)(smc + OFF_YHI + o0) = *(uint32_t*)&w0;
                *(uint32_t*)(smc + OFF_YHI + o1) = *(uint32_t*)&w1;
                *(uint32_t*)(smc + OFF_YLO + o0) =
                    pack_f16(y0 - __half2float(h0), y1 - __half2float(h1));
                *(uint32_t*)(smc + OFF_YLO + o1) =
                    pack_f16(y2 - __half2float(h2), y3 - __half2float(h3));
            }
            fold_corr(cV, cVc[0], cVc[1]);
            const int dv = nh * 8 + tg * 2;
            float b0 = bv[h * DVD + dv], b1 = bv[h * DVD + dv + 1];
            float* v0 = sVf + (rbase + g) * 16 + dv;
            float* v1 = sVf + (rbase + 8 + g) * 16 + dv;
            v0[0] = cV[0] + b0;  v0[1] = cV[1] + b1;
            v1[0] = cV[2] + b0;  v1[1] = cV[3] + b1;
        }
        __syncthreads();                                   // ---- s2 ----

        // ======== GEMM2 + softmax (warps 0-3 only) ========
        if (wid < 4) {
            float cS[7][4];
            uint32_t cSc[7][2];
            #pragma unroll
            for (int n = 0; n < 7; n++) {
                #pragma unroll
                for (int q = 0; q < 4; q++) cS[n][q] = 0.f;
                cSc[n][0] = 0u; cSc[n][1] = 0u;
            }
            #pragma unroll
            for (int k = 0; k < 8; k++) {
                uint32_t ca = (uint32_t)(((2 * k + ahalf) ^ lr) << 4);
                uint32_t ahi[4], alo[4];
                ldsm_x4(ahi, sb + OFF_XHI + aRow2 + ca);
                ldsm_x4(alo, sb + OFF_XLO + aRow2 + ca);
                uint32_t cb = (uint32_t)(((2 * k + bhalf) ^ blr) << 4);
                uint32_t bo = bRowOff + cb;
                #pragma unroll
                for (int np = 0; np < 3; np++) {
                    uint32_t o = bo + bPair + (uint32_t)(np * 4096);
                    uint32_t bh[4], bl[4];
                    ldsm_x4(bh, sb + OFF_YHI + o);
                    ldsm_x4(bl, sb + OFF_YLO + o);
                    const int n0 = np * 2, n1 = np * 2 + 1;
                    mma_f32(cS[n0], ahi, bh[0], bh[1]);
                    mma_f16(cSc[n0][0], cSc[n0][1], ahi, bl[0], bl[1]);
                    mma_f16(cSc[n0][0], cSc[n0][1], alo, bh[0], bh[1]);
                    mma_f32(cS[n1], ahi, bh[2], bh[3]);
                    mma_f16(cSc[n1][0], cSc[n1][1], ahi, bl[2], bl[3]);
                    mma_f16(cSc[n1][0], cSc[n1][1], alo, bh[2], bh[3]);
                }
                {
                    uint32_t o = bo + (uint32_t)(6 * 2048);
                    uint32_t bh[2], bl[2];
                    ldsm_x2(bh, sb + OFF_YHI + o);
                    ldsm_x2(bl, sb + OFF_YLO + o);
                    mma_f32(cS[6], ahi, bh[0], bh[1]);
                    mma_f16(cSc[6][0], cSc[6][1], ahi, bl[0], bl[1]);
                    mma_f16(cSc[6][0], cSc[6][1], alo, bh[0], bh[1]);
                }
            }
            #pragma unroll
            for (int n = 0; n < 7; n++) fold_corr(cS[n], cSc[n][0], cSc[n][1]);

            // ---- bias + leaky + softmax over l, P -> smem ----
            #pragma unroll
            for (int pair = 0; pair < 2; pair++) {
                const int m = wid * 16 + pair * 8 + g;
                const float rm = srf[m * 8 + h];
                float vals[14];
                float mx = -1e30f;
                #pragma unroll
                for (int n = 0; n < 7; n++) {
                    #pragma unroll
                    for (int j = 0; j < 2; j++) {
                        int l = n * 8 + tg * 2 + j;
                        float v = cS[n][pair * 2 + j] + spf[l * 8 + h] + rm;
                        v = v > 0.f ? v : 0.1f * v;
                        if (l >= LL) v = -1e30f;
                        vals[n * 2 + j] = v;
                        mx = fmaxf(mx, v);
                    }
                }
                mx = fmaxf(mx, __shfl_xor_sync(0xffffffffu, mx, 1));
                mx = fmaxf(mx, __shfl_xor_sync(0xffffffffu, mx, 2));
                float sum = 0.f;
                #pragma unroll
                for (int q = 0; q < 14; q++) {
                    float e = __expf(vals[q] - mx);
                    vals[q] = e;
                    sum += e;
                }
                sum += __shfl_xor_sync(0xffffffffu, sum, 1);
                sum += __shfl_xor_sync(0xffffffffu, sum, 2);
                float inv = 1.f / sum;
                float* prow = sPf + m * 65;
                #pragma unroll
                for (int n = 0; n < 7; n++) {
                    prow[n * 8 + tg * 2]     = vals[n * 2] * inv;
                    prow[n * 8 + tg * 2 + 1] = vals[n * 2 + 1] * inv;
                }
            }
        }
        __syncthreads();                                   // ---- s3 ----

        // ======== out = relu(Pᵀ·V), store head slice (all threads) ========
        {
            int l = tid >> 2, dv = (tid & 3) * 4;
            if (l < LL) {
                float4 acc = make_float4(0.f, 0.f, 0.f, 0.f);
                const float* pcol = sPf + l;
                const float* vb   = sVf + dv;
                #pragma unroll 10
                for (int m = 0; m < LL; m++) {
                    float p = pcol[m * 65];
                    float4 vv = *(const float4*)(vb + m * 16);
                    acc.x += p * vv.x;  acc.y += p * vv.y;
                    acc.z += p * vv.z;  acc.w += p * vv.w;
                }
                acc.x = fmaxf(acc.x, 0.f);  acc.y = fmaxf(acc.y, 0.f);
                acc.z = fmaxf(acc.z, 0.f);  acc.w = fmaxf(acc.w, 0.f);
                *(float4*)(out + (long long)bid * (LL * NH * DVD)
                               + l * (NH * DVD) + h * DVD + dv) = acc;
            }
        }
        __syncthreads();                                   // ---- s4 ----
    }
}

// ---------------------------------------------------------------------------
extern "C" void kernel_launch(void* const* d_in, const int* in_sizes, int n_in,
                              void* d_out, int out_size) {
    const float* hid = (const float*)d_in[0];
    const float* Wq  = (const float*)d_in[1];
    const float* bq  = (const float*)d_in[2];
    const float* Wk  = (const float*)d_in[3];
    const float* bk  = (const float*)d_in[4];
    const float* Wv  = (const float*)d_in[5];
    const float* bv  = (const float*)d_in[6];
    float* out = (float*)d_out;

    const int nb = in_sizes[0] / (LL * FD);

    cudaFuncSetAttribute(precompute2_kernel,
                         cudaFuncAttributeMaxDynamicSharedMemorySize, P2_SMEM);
    cudaFuncSetAttribute(attn_mma_kernel,
                         cudaFuncAttributeMaxDynamicSharedMemorySize, SMEM_TOTAL);

    precompute1_kernel<<<dim3(NH, 8), 256>>>(Wq, bq, Wk, bk);
    precompute2_kernel<<<NH, NT, P2_SMEM>>>(Wv);
    attn_mma_kernel<<<nb, NT, SMEM_TOTAL>>>(hid, bv, out);
}

// round 14
// speedup vs baseline: 1.2236x; 1.2236x over previous
#include <cuda_runtime.h>
#include <cuda_fp16.h>
#include <cstdint>

#define NH   8
#define FD   128
#define DVD  16
#define LL   50
#define NT   256

// ---------------- smem layout (bytes) ----------------
#define OFF_SP   0                      // p_all [2][64][8] f32 (+c folded)
#define OFF_SR   4096                   // r_all [2][64][8] f32
#define OFF_XHI  8192                   // X hi [128][256B] swizzled fp16
#define OFF_XLO  (OFF_XHI + 32768)
#define OFF_AHI  (OFF_XLO + 32768)      // At hi (per head, prefetched)
#define OFF_ALO  (OFF_AHI + 32768)      // At lo
#define OFF_WHI  (OFF_ALO + 32768)      // Wvt hi [16][256B]
#define OFF_WLO  (OFF_WHI + 4096)
#define OFF_YHI  (OFF_WLO + 4096)       // Y hi [128][256B] swizzled
#define OFF_V    (OFF_YHI + 32768)      // V f32 [2][64][16]
#define OFF_P    (OFF_V + 8192)         // Ylo (GEMM phase) / P f32 [2][64][65]
#define SMEM_TOTAL (OFF_P + 2*64*65*4)  // 221696

// ------------- precomputed folded weights (fp16 hi/lo) -------------
__device__ __align__(16) __half g_Ahi[NH][128 * 128];
__device__ __align__(16) __half g_Alo[NH][128 * 128];
__device__ __align__(16) __half g_Whi[NH][16 * 128];
__device__ __align__(16) __half g_Wlo[NH][16 * 128];
__device__ float g_u[NH][FD];
__device__ float g_w[NH][FD];
__device__ float g_c[NH];

// swizzled byte offset in a [rows][128 f16] tile (256B rows, 16B-chunk XOR)
__host__ __device__ __forceinline__ uint32_t xoff(int r, int c) {
    return (uint32_t)r * 256u
         + (uint32_t)(((((c >> 3) ^ (r & 7))) << 4) + (c & 7) * 2);
}

// ---------------- PTX helpers ----------------
__device__ __forceinline__ uint32_t smem_u32(const void* p) {
    uint32_t a;
    asm("{ .reg .u64 t; cvta.to.shared.u64 t, %1; cvt.u32.u64 %0, t; }"
        : "=r"(a) : "l"(p));
    return a;
}
__device__ __forceinline__ void ldsm_x4(uint32_t a[4], uint32_t addr) {
    asm volatile("ldmatrix.sync.aligned.m8n8.x4.shared.b16 {%0,%1,%2,%3}, [%4];"
                 : "=r"(a[0]), "=r"(a[1]), "=r"(a[2]), "=r"(a[3]) : "r"(addr));
}
__device__ __forceinline__ void ldsm_x2(uint32_t a[2], uint32_t addr) {
    asm volatile("ldmatrix.sync.aligned.m8n8.x2.shared.b16 {%0,%1}, [%2];"
                 : "=r"(a[0]), "=r"(a[1]) : "r"(addr));
}
// main term: f16 x f16 -> f32 accum
__device__ __forceinline__ void mma_f32(float c[4], const uint32_t a[4],
                                        const uint32_t b0, const uint32_t b1) {
    asm volatile(
        "mma.sync.aligned.m16n8k16.row.col.f32.f16.f16.f32 "
        "{%0,%1,%2,%3}, {%4,%5,%6,%7}, {%8,%9}, {%0,%1,%2,%3};"
        : "+f"(c[0]), "+f"(c[1]), "+f"(c[2]), "+f"(c[3])
        : "r"(a[0]), "r"(a[1]), "r"(a[2]), "r"(a[3]), "r"(b0), "r"(b1));
}
// correction terms: f16 x f16 -> f16 accum (2x f32-accum rate)
__device__ __forceinline__ void mma_f16(uint32_t& d0, uint32_t& d1,
                                        const uint32_t a[4],
                                        const uint32_t b0, const uint32_t b1) {
    asm volatile(
        "mma.sync.aligned.m16n8k16.row.col.f16.f16.f16.f16 "
        "{%0,%1}, {%2,%3,%4,%5}, {%6,%7}, {%0,%1};"
        : "+r"(d0), "+r"(d1)
        : "r"(a[0]), "r"(a[1]), "r"(a[2]), "r"(a[3]), "r"(b0), "r"(b1));
}
__device__ __forceinline__ void fold_corr(float c[4], uint32_t d0, uint32_t d1) {
    float2 f0 = __half22float2(*(__half2*)&d0);
    float2 f1 = __half22float2(*(__half2*)&d1);
    c[0] += f0.x;  c[1] += f0.y;  c[2] += f1.x;  c[3] += f1.y;
}
#define CP_ASYNC16(s, g) \
    asm volatile("cp.async.cg.shared.global [%0], [%1], 16;" :: "r"(s), "l"(g))
#define CP_COMMIT() asm volatile("cp.async.commit_group;" ::: "memory")
#define CP_WAIT0()  asm volatile("cp.async.wait_group 0;" ::: "memory")

__device__ __forceinline__ uint32_t pack_f16(float a, float b) {
    __half2 t = __floats2half2_rn(a, b);
    return *(uint32_t*)&t;
}

// ---------------------------------------------------------------------------
// Kernel 1: fold A = Wq Wk^T (fp16 hi/lo, swizzled At), Wvt hi/lo, biases.
// grid (NH, 64): 1 output element per thread, 4-way ILP on the e-reduction.
// ---------------------------------------------------------------------------
__global__ void __launch_bounds__(NT)
precompute_kernel(const float* __restrict__ Wq,
                  const float* __restrict__ bq,
                  const float* __restrict__ Wk,
                  const float* __restrict__ bk,
                  const float* __restrict__ Wv) {
    const int h     = blockIdx.x;
    const int slice = blockIdx.y;
    const int tid   = threadIdx.x;
    const float* wq = Wq + h * FD * 128;
    const float* wk = Wk + h * FD * 128;

    // ---- A[f][fp] = sum_e Wq[f][e] * Wk[fp][e], 1 element/thread ----
    {
        const int o  = slice * NT + tid;      // 0..16383
        const int f  = o >> 7;
        const int fp = o & 127;
        const float4* qrow = (const float4*)(wq + f * 128);
        const float4* krow = (const float4*)(wk + fp * 128);
        float a0 = 0.f, a1 = 0.f, a2 = 0.f, a3 = 0.f;
        #pragma unroll
        for (int e4 = 0; e4 < 32; e4 += 4) {
            float4 q0 = qrow[e4],     k0 = krow[e4];
            float4 q1 = qrow[e4 + 1], k1 = krow[e4 + 1];
            float4 q2 = qrow[e4 + 2], k2 = krow[e4 + 2];
            float4 q3 = qrow[e4 + 3], k3 = krow[e4 + 3];
            a0 += q0.x * k0.x + q0.y * k0.y + q0.z * k0.z + q0.w * k0.w;
            a1 += q1.x * k1.x + q1.y * k1.y + q1.z * k1.z + q1.w * k1.w;
            a2 += q2.x * k2.x + q2.y * k2.y + q2.z * k2.z + q2.w * k2.w;
            a3 += q3.x * k3.x + q3.y * k3.y + q3.z * k3.z + q3.w * k3.w;
        }
        float acc = (a0 + a1) + (a2 + a3);
        __half hi = __float2half_rn(acc);
        float rem = acc - __half2float(hi);
        uint32_t off = xoff(fp, f);          // At[fp][f]
        *(__half*)((char*)g_Ahi[h] + off) = hi;
        *(__half*)((char*)g_Alo[h] + off) = __float2half_rn(rem);
    }

    // ---- slice 0: Wvt split;  slice 1: bias dots ----
    if (slice == 0) {
        #pragma unroll
        for (int it = 0; it < 8; it++) {
            int idx = it * NT + tid;          // 0..2047
            int dv = idx >> 7, f = idx & 127;
            float v = Wv[h * FD * DVD + f * DVD + dv];
            __half hi = __float2half_rn(v);
            float rem = v - __half2float(hi);
            uint32_t off = xoff(dv, f);
            *(__half*)((char*)g_Whi[h] + off) = hi;
            *(__half*)((char*)g_Wlo[h] + off) = __float2half_rn(rem);
        }
    } else if (slice == 1) {
        if (tid < FD) {
            const float4* qrow = (const float4*)(wq + tid * 128);
            const float4* krow = (const float4*)(wk + tid * 128);
            const float4* bkv  = (const float4*)(bk + h * 128);
            const float4* bqv  = (const float4*)(bq + h * 128);
            float au = 0.f, aw = 0.f;
            #pragma unroll
            for (int e4 = 0; e4 < 32; e4++) {
                float4 q = qrow[e4], k = krow[e4];
                float4 bb = bkv[e4], bs = bqv[e4];
                au += q.x * bb.x + q.y * bb.y + q.z * bb.z + q.w * bb.w;
                aw += k.x * bs.x + k.y * bs.y + k.z * bs.z + k.w * bs.w;
            }
            g_u[h][tid] = au;
            g_w[h][tid] = aw;
        } else if (tid == 128) {
            const float4* bqv = (const float4*)(bq + h * 128);
            const float4* bkv = (const float4*)(bk + h * 128);
            float c = 0.f;
            #pragma unroll
            for (int e4 = 0; e4 < 32; e4++) {
                float4 a = bqv[e4], b = bkv[e4];
                c += a.x * b.x + a.y * b.y + a.z * b.z + a.w * b.w;
            }
            g_c[h] = c;
        }
    }
}

// ---------------------------------------------------------------------------
// Kernel 2: HMMA attention, 256 threads, 2 batches per CTA (M = 128 rows).
// fp16 hi/lo; main f32-accum + deferred f16-accum corrections.
// B-operands loaded pairwise via ldmatrix.x4; GEMM2 skips fully-masked tile 7.
// ---------------------------------------------------------------------------
__global__ void __launch_bounds__(NT, 1)
attn_mma_kernel(const float* __restrict__ hid,
                const float* __restrict__ bv,
                float* __restrict__ out) {
    extern __shared__ char smc[];
    const uint32_t sb = smem_u32(smc);
    const int tid  = threadIdx.x;
    const int wid  = tid >> 5;
    const int lane = tid & 31;
    const int bid  = blockIdx.x;

    float* spf = (float*)(smc + OFF_SP);   // [2][64][8]
    float* srf = (float*)(smc + OFF_SR);   // [2][64][8]
    float* sVf = (float*)(smc + OFF_V);
    float* sPf = (float*)(smc + OFF_P);

    // ---- load x (2 batches), fp16 hi/lo split, swizzled ----
    for (int i = tid; i < 128 * 64; i += NT) {
        int row = i >> 6;
        int cp  = (i & 63) * 2;
        int bb = row >> 6, l = row & 63;
        float v0 = 0.f, v1 = 0.f;
        if (l < LL) {
            const float* xr = hid + (long long)(2 * bid + bb) * (LL * FD) + l * FD + cp;
            v0 = xr[0]; v1 = xr[1];
        }
        __half h0 = __float2half_rn(v0), h1 = __float2half_rn(v1);
        float r0 = v0 - __half2float(h0), r1 = v1 - __half2float(h1);
        uint32_t off = xoff(row, cp);
        __half2 hw = __halves2half2(h0, h1);
        *(uint32_t*)(smc + OFF_XHI + off) = *(uint32_t*)&hw;
        *(uint32_t*)(smc + OFF_XLO + off) = pack_f16(r0, r1);
    }

    // ---- prologue: prefetch head 0 weights ----
    {
        const char* gh = (const char*)g_Ahi[0];
        const char* gl = (const char*)g_Alo[0];
        #pragma unroll
        for (int j = 0; j < 8; j++) {
            uint32_t o = (uint32_t)(j * 4096 + tid * 16);
            CP_ASYNC16(sb + OFF_AHI + o, gh + o);
            CP_ASYNC16(sb + OFF_ALO + o, gl + o);
        }
        CP_ASYNC16(sb + OFF_WHI + tid * 16, (const char*)g_Whi[0] + tid * 16);
        CP_ASYNC16(sb + OFF_WLO + tid * 16, (const char*)g_Wlo[0] + tid * 16);
        CP_COMMIT();
    }

    // ---- all-head p/r bias dots, once (overlaps prefetch) ----
    {
        int bb = tid >> 7;
        int l  = (tid >> 1) & 63;
        int pr = tid & 1;
        float acc[8];
        #pragma unroll
        for (int h2 = 0; h2 < 8; h2++) acc[h2] = 0.f;
        if (l < LL) {
            const float* xr = hid + (long long)(2 * bid + bb) * (LL * FD) + l * FD;
            const float* vb = pr ? &g_w[0][0] : &g_u[0][0];
            #pragma unroll 2
            for (int f = 0; f < FD; f += 4) {
                float4 xq = *(const float4*)(xr + f);
                #pragma unroll
                for (int h2 = 0; h2 < 8; h2++) {
                    const float* v = vb + h2 * FD + f;
                    acc[h2] += xq.x * v[0] + xq.y * v[1] + xq.z * v[2] + xq.w * v[3];
                }
            }
        }
        float* dst = pr ? srf : spf;
        #pragma unroll
        for (int h2 = 0; h2 < 8; h2++)
            dst[((bb << 6) + l) * 8 + h2] = acc[h2] + (pr ? 0.f : g_c[h2]);
    }

    // ---- ldmatrix lane-address components ----
    const int lr   = lane & 7;
    const int quad = lane >> 3;
    const int ahalf = quad >> 1;
    const int i15  = lane & 15;
    const int blr  = i15 & 7;
    const int bhalf = i15 >> 3;
    const uint32_t bRowOff = (uint32_t)blr * 256u;
    const uint32_t bPair   = (uint32_t)((lane >> 4) << 11);  // +2048B for 2nd tile
    const int g  = lane >> 2;
    const int tg = lane & 3;

    // GEMM1: 4 m-slices (m32) x 2 n-halves; 2 passes of 4 n-tiles each
    const int ms = wid & 3;
    const int nh = wid >> 2;
    const uint32_t aRow1 = (uint32_t)(ms * 32 + lr + ((quad & 1) << 3)) * 256u;
    // GEMM2: m16 per warp, all n of batch bb2
    const uint32_t aRow2 = (uint32_t)(wid * 16 + lr + ((quad & 1) << 3)) * 256u;
    const int bb2 = wid >> 2;

    for (int h = 0; h < NH; h++) {
        CP_WAIT0();
        __syncthreads();                                   // ---- s1 ----

        // ======== GEMM1: Y = X·Atᵀ + V rider, 2 passes of 4 tiles ========
        #pragma unroll
        for (int pass = 0; pass < 2; pass++) {
            float cY[2][4][4];
            uint32_t cc[2][4][2];
            float cV[2][4];
            uint32_t cVc[2][2];
            #pragma unroll
            for (int mt = 0; mt < 2; mt++) {
                #pragma unroll
                for (int j = 0; j < 4; j++) {
                    #pragma unroll
                    for (int q = 0; q < 4; q++) cY[mt][j][q] = 0.f;
                    cc[mt][j][0] = 0u; cc[mt][j][1] = 0u;
                }
                #pragma unroll
                for (int q = 0; q < 4; q++) cV[mt][q] = 0.f;
                cVc[mt][0] = 0u; cVc[mt][1] = 0u;
            }

            #pragma unroll
            for (int k = 0; k < 8; k++) {
                uint32_t ca = (uint32_t)(((2 * k + ahalf) ^ lr) << 4);
                uint32_t ahi0[4], alo0[4], ahi1[4], alo1[4];
                ldsm_x4(ahi0, sb + OFF_XHI + aRow1 + ca);
                ldsm_x4(alo0, sb + OFF_XLO + aRow1 + ca);
                ldsm_x4(ahi1, sb + OFF_XHI + aRow1 + 4096u + ca);
                ldsm_x4(alo1, sb + OFF_XLO + aRow1 + 4096u + ca);
                uint32_t cb = (uint32_t)(((2 * k + bhalf) ^ blr) << 4);
                uint32_t bo = bRowOff + cb + bPair;
                #pragma unroll
                for (int jp = 0; jp < 2; jp++) {   // tile pair (2 n-tiles per x4)
                    uint32_t o = bo + (uint32_t)((nh * 8 + pass * 4 + jp * 2) * 2048);
                    uint32_t bh[4], bl[4];
                    ldsm_x4(bh, sb + OFF_AHI + o);
                    ldsm_x4(bl, sb + OFF_ALO + o);
                    const int j0 = jp * 2, j1 = jp * 2 + 1;
                    mma_f32(cY[0][j0], ahi0, bh[0], bh[1]);
                    mma_f16(cc[0][j0][0], cc[0][j0][1], ahi0, bl[0], bl[1]);
                    mma_f16(cc[0][j0][0], cc[0][j0][1], alo0, bh[0], bh[1]);
                    mma_f32(cY[1][j0], ahi1, bh[0], bh[1]);
                    mma_f16(cc[1][j0][0], cc[1][j0][1], ahi1, bl[0], bl[1]);
                    mma_f16(cc[1][j0][0], cc[1][j0][1], alo1, bh[0], bh[1]);
                    mma_f32(cY[0][j1], ahi0, bh[2], bh[3]);
                    mma_f16(cc[0][j1][0], cc[0][j1][1], ahi0, bl[2], bl[3]);
                    mma_f16(cc[0][j1][0], cc[0][j1][1], alo0, bh[2], bh[3]);
                    mma_f32(cY[1][j1], ahi1, bh[2], bh[3]);
                    mma_f16(cc[1][j1][0], cc[1][j1][1], ahi1, bl[2], bl[3]);
                    mma_f16(cc[1][j1][0], cc[1][j1][1], alo1, bh[2], bh[3]);
                }
                if (pass == 0) {
                    uint32_t o = bRowOff + cb + (uint32_t)(nh * 2048);
                    uint32_t bh[2], bl[2];
                    ldsm_x2(bh, sb + OFF_WHI + o);
                    ldsm_x2(bl, sb + OFF_WLO + o);
                    mma_f32(cV[0], ahi0, bh[0], bh[1]);
                    mma_f16(cVc[0][0], cVc[0][1], ahi0, bl[0], bl[1]);
                    mma_f16(cVc[0][0], cVc[0][1], alo0, bh[0], bh[1]);
                    mma_f32(cV[1], ahi1, bh[0], bh[1]);
                    mma_f16(cVc[1][0], cVc[1][1], ahi1, bl[0], bl[1]);
                    mma_f16(cVc[1][0], cVc[1][1], alo1, bh[0], bh[1]);
                }
            }

            // fold + write this pass's Y tiles (hi->YHI, lo->P) and V
            #pragma unroll
            for (int mt = 0; mt < 2; mt++) {
                const int rbase = ms * 32 + mt * 16;
                #pragma unroll
                for (int j = 0; j < 4; j++) {
                    fold_corr(cY[mt][j], cc[mt][j][0], cc[mt][j][1]);
                    int col = nh * 64 + (pass * 4 + j) * 8 + tg * 2;
                    uint32_t o0 = xoff(rbase + g, col);
                    uint32_t o1 = xoff(rbase + 8 + g, col);
                    float y0 = cY[mt][j][0], y1 = cY[mt][j][1];
                    float y2 = cY[mt][j][2], y3 = cY[mt][j][3];
                    __half h0 = __float2half_rn(y0), h1 = __float2half_rn(y1);
                    __half h2 = __float2half_rn(y2), h3 = __float2half_rn(y3);
                    __half2 w0 = __halves2half2(h0, h1);
                    __half2 w1 = __halves2half2(h2, h3);
                    *(uint32_t*)(smc + OFF_YHI + o0) = *(uint32_t*)&w0;
                    *(uint32_t*)(smc + OFF_YHI + o1) = *(uint32_t*)&w1;
                    *(uint32_t*)(smc + OFF_P + o0) =
                        pack_f16(y0 - __half2float(h0), y1 - __half2float(h1));
                    *(uint32_t*)(smc + OFF_P + o1) =
                        pack_f16(y2 - __half2float(h2), y3 - __half2float(h3));
                }
                if (pass == 0) {
                    fold_corr(cV[mt], cVc[mt][0], cVc[mt][1]);
                    const int dv = nh * 8 + tg * 2;
                    const int bb = rbase >> 6, ml = (rbase & 63) + g;
                    float b0 = bv[h * DVD + dv], b1 = bv[h * DVD + dv + 1];
                    float* v0 = sVf + (bb * 64 + ml) * 16 + dv;
                    float* v1 = sVf + (bb * 64 + ml + 8) * 16 + dv;
                    v0[0] = cV[mt][0] + b0;  v0[1] = cV[mt][1] + b1;
                    v1[0] = cV[mt][2] + b0;  v1[1] = cV[mt][3] + b1;
                }
            }
        }
        __syncthreads();                                   // ---- s2 ----

        // ======== prefetch next head's At/Wvt ========
        if (h + 1 < NH) {
            const char* gh = (const char*)g_Ahi[h + 1];
            const char* gl = (const char*)g_Alo[h + 1];
            #pragma unroll
            for (int j = 0; j < 8; j++) {
                uint32_t o = (uint32_t)(j * 4096 + tid * 16);
                CP_ASYNC16(sb + OFF_AHI + o, gh + o);
                CP_ASYNC16(sb + OFF_ALO + o, gl + o);
            }
            CP_ASYNC16(sb + OFF_WHI + tid * 16, (const char*)g_Whi[h + 1] + tid * 16);
            CP_ASYNC16(sb + OFF_WLO + tid * 16, (const char*)g_Wlo[h + 1] + tid * 16);
            CP_COMMIT();
        }

        // ======== GEMM2: C2[m,l] = X·Yᵀ, 7 n-tiles (tile 7 fully masked) ====
        float cS[7][4];
        uint32_t cSc[7][2];
        #pragma unroll
        for (int n = 0; n < 7; n++) {
            #pragma unroll
            for (int q = 0; q < 4; q++) cS[n][q] = 0.f;
            cSc[n][0] = 0u; cSc[n][1] = 0u;
        }
        const uint32_t ybase = (uint32_t)(bb2 * 64 * 256);
        #pragma unroll
        for (int k = 0; k < 8; k++) {
            uint32_t ca = (uint32_t)(((2 * k + ahalf) ^ lr) << 4);
            uint32_t ahi[4], alo[4];
            ldsm_x4(ahi, sb + OFF_XHI + aRow2 + ca);
            ldsm_x4(alo, sb + OFF_XLO + aRow2 + ca);
            uint32_t cb = (uint32_t)(((2 * k + bhalf) ^ blr) << 4);
            uint32_t bo = ybase + bRowOff + cb;
            #pragma unroll
            for (int np = 0; np < 3; np++) {   // tile pairs (0,1)(2,3)(4,5)
                uint32_t o = bo + bPair + (uint32_t)(np * 2 * 2048);
                uint32_t bh[4], bl[4];
                ldsm_x4(bh, sb + OFF_YHI + o);
                ldsm_x4(bl, sb + OFF_P + o);
                const int n0 = np * 2, n1 = np * 2 + 1;
                mma_f32(cS[n0], ahi, bh[0], bh[1]);
                mma_f16(cSc[n0][0], cSc[n0][1], ahi, bl[0], bl[1]);
                mma_f16(cSc[n0][0], cSc[n0][1], alo, bh[0], bh[1]);
                mma_f32(cS[n1], ahi, bh[2], bh[3]);
                mma_f16(cSc[n1][0], cSc[n1][1], ahi, bl[2], bl[3]);
                mma_f16(cSc[n1][0], cSc[n1][1], alo, bh[2], bh[3]);
            }
            {   // tile 6 alone
                uint32_t o = bo + (uint32_t)(6 * 2048);
                uint32_t bh[2], bl[2];
                ldsm_x2(bh, sb + OFF_YHI + o);
                ldsm_x2(bl, sb + OFF_P + o);
                mma_f32(cS[6], ahi, bh[0], bh[1]);
                mma_f16(cSc[6][0], cSc[6][1], ahi, bl[0], bl[1]);
                mma_f16(cSc[6][0], cSc[6][1], alo, bh[0], bh[1]);
            }
        }
        #pragma unroll
        for (int n = 0; n < 7; n++) fold_corr(cS[n], cSc[n][0], cSc[n][1]);
        __syncthreads();                                   // ---- s3 ----

        // ======== bias + leaky + softmax over l, P -> smem ========
        {
            const int mbase = ((wid & 3) << 4) + g;
            #pragma unroll
            for (int pair = 0; pair < 2; pair++) {
                const int m = mbase + pair * 8;
                const float rm = srf[((bb2 << 6) + m) * 8 + h];
                float vals[14];
                float mx = -1e30f;
                #pragma unroll
                for (int n = 0; n < 7; n++) {
                    #pragma unroll
                    for (int j = 0; j < 2; j++) {
                        int l = n * 8 + tg * 2 + j;
                        float v = cS[n][pair * 2 + j]
                                + spf[((bb2 << 6) + l) * 8 + h] + rm;
                        v = v > 0.f ? v : 0.1f * v;
                        if (l >= LL) v = -1e30f;
                        vals[n * 2 + j] = v;
                        mx = fmaxf(mx, v);
                    }
                }
                mx = fmaxf(mx, __shfl_xor_sync(0xffffffffu, mx, 1));
                mx = fmaxf(mx, __shfl_xor_sync(0xffffffffu, mx, 2));
                float sum = 0.f;
                #pragma unroll
                for (int q = 0; q < 14; q++) {
                    float e = __expf(vals[q] - mx);
                    vals[q] = e;
                    sum += e;
                }
                sum += __shfl_xor_sync(0xffffffffu, sum, 1);
                sum += __shfl_xor_sync(0xffffffffu, sum, 2);
                float inv = 1.f / sum;
                float* prow = sPf + (bb2 * 64 + m) * 65;
                #pragma unroll
                for (int n = 0; n < 7; n++) {
                    prow[n * 8 + tg * 2]     = vals[n * 2] * inv;
                    prow[n * 8 + tg * 2 + 1] = vals[n * 2 + 1] * inv;
                }
            }
        }
        __syncthreads();                                   // ---- s4 ----

        // ======== out = relu(Pᵀ·V), store head slice ========
        #pragma unroll
        for (int it = 0; it < 2; it++) {
            int item = tid + it * NT;
            int b2 = item >> 8, l = (item >> 2) & 63, dv = (item & 3) * 4;
            if (l < LL) {
                float4 acc = make_float4(0.f, 0.f, 0.f, 0.f);
                const float* pcol = sPf + b2 * 64 * 65 + l;
                const float* vb   = sVf + b2 * 1024 + dv;
                #pragma unroll 10
                for (int m = 0; m < LL; m++) {
                    float p = pcol[m * 65];
                    float4 vv = *(const float4*)(vb + m * 16);
                    acc.x += p * vv.x;  acc.y += p * vv.y;
                    acc.z += p * vv.z;  acc.w += p * vv.w;
                }
                acc.x = fmaxf(acc.x, 0.f);  acc.y = fmaxf(acc.y, 0.f);
                acc.z = fmaxf(acc.z, 0.f);  acc.w = fmaxf(acc.w, 0.f);
                *(float4*)(out + (long long)(2 * bid + b2) * (LL * NH * DVD)
                               + l * (NH * DVD) + h * DVD + dv) = acc;
            }
        }
    }
}

// ---------------------------------------------------------------------------
extern "C" void kernel_launch(void* const* d_in, const int* in_sizes, int n_in,
                              void* d_out, int out_size) {
    const float* hid = (const float*)d_in[0];
    const float* Wq  = (const float*)d_in[1];
    const float* bq  = (const float*)d_in[2];
    const float* Wk  = (const float*)d_in[3];
    const float* bk  = (const float*)d_in[4];
    const float* Wv  = (const float*)d_in[5];
    const float* bv  = (const float*)d_in[6];
    float* out = (float*)d_out;

    const int nb = in_sizes[0] / (LL * FD);

    cudaFuncSetAttribute(attn_mma_kernel,
                         cudaFuncAttributeMaxDynamicSharedMemorySize, SMEM_TOTAL);

    precompute_kernel<<<dim3(NH, 64), NT>>>(Wq, bq, Wk, bk, Wv);
    attn_mma_kernel<<<nb / 2, NT, SMEM_TOTAL>>>(hid, bv, out);
}